// round 11
// baseline (speedup 1.0000x reference)
#include <cuda_runtime.h>
#include <cstdint>

#define Bn 16
#define Vn 40000
#define Cn 128
#define Hn 56
#define Wn 56
#define En 120000
#define Mn (Bn*Vn)          // 640000
#define HWn (Hn*Wn)         // 3136

// ---------------- device scratch ----------------
__device__ float g_imgT[(size_t)Bn*HWn*Cn];     // [B,H,W,C]
__device__ float g_A [81920000];                // G, later U (tf32-rounded)
__device__ float g_Dk[81920000];                // D (tf32-rounded; residual)
__device__ float g_T0[81920000];                // X@W0+b0
__device__ float g_T1[81920000];                // X@W1
__device__ float g_Bt[6*128*128];               // transposed tf32 weights [n][k]

__device__ int g_deg[Vn];
__device__ int g_cursor[Vn];
__device__ int g_rowptr[Vn+1];
__device__ int g_col[2*En];

// ---------------- helpers ----------------
__device__ __forceinline__ float rnd_tf32(float x) {
    float r;
    asm("cvt.rna.tf32.f32 %0, %1;" : "=f"(r) : "f"(x));
    return r;
}

__device__ __forceinline__ uint32_t smem_u32(const void* p) {
    uint32_t a;
    asm("{ .reg .u64 t; cvta.to.shared.u64 t, %1; cvt.u32.u64 %0, t; }" : "=r"(a) : "l"(p));
    return a;
}

__device__ __forceinline__ void mma_tf32(float* c, const uint32_t* a, const uint32_t* b) {
    asm volatile(
        "mma.sync.aligned.m16n8k8.row.col.f32.tf32.tf32.f32 "
        "{%0,%1,%2,%3}, {%4,%5,%6,%7}, {%8,%9}, {%0,%1,%2,%3};"
        : "+f"(c[0]), "+f"(c[1]), "+f"(c[2]), "+f"(c[3])
        : "r"(a[0]), "r"(a[1]), "r"(a[2]), "r"(a[3]), "r"(b[0]), "r"(b[1]));
}

// ---------------- CSR build ----------------
__global__ void zero_csr() {
    int i = blockIdx.x*blockDim.x + threadIdx.x;
    if (i < Vn) { g_deg[i] = 0; g_cursor[i] = 0; }
}

__global__ void count_edges(const int* __restrict__ edges) {
    int e = blockIdx.x*blockDim.x + threadIdx.x;
    if (e < En) {
        atomicAdd(&g_deg[edges[2*e+0]], 1);
        atomicAdd(&g_deg[edges[2*e+1]], 1);
    }
}

__global__ void scan_kernel() {
    __shared__ int partial[1024];
    int t = threadIdx.x;
    const int CH = (Vn + 1023) / 1024;
    int base = t * CH;
    int s = 0;
    for (int i = 0; i < CH; i++) {
        int idx = base + i;
        if (idx < Vn) s += g_deg[idx];
    }
    partial[t] = s;
    __syncthreads();
    for (int off = 1; off < 1024; off <<= 1) {
        int v = 0;
        if (t >= off) v = partial[t - off];
        __syncthreads();
        partial[t] += v;
        __syncthreads();
    }
    int run = (t == 0) ? 0 : partial[t-1];
    for (int i = 0; i < CH; i++) {
        int idx = base + i;
        if (idx < Vn) { g_rowptr[idx] = run; run += g_deg[idx]; }
    }
    if (t == 1023) g_rowptr[Vn] = run;
}

__global__ void fill_edges(const int* __restrict__ edges) {
    int e = blockIdx.x*blockDim.x + threadIdx.x;
    if (e < En) {
        int i = edges[2*e+0], j = edges[2*e+1];
        int p = atomicAdd(&g_cursor[i], 1);
        g_col[g_rowptr[i] + p] = j;
        int q = atomicAdd(&g_cursor[j], 1);
        g_col[g_rowptr[j] + q] = i;
    }
}

// ---------------- weight prep: all 6 matrices in one launch ----------------
__global__ void prep_weights_all(const float* __restrict__ W0_1, const float* __restrict__ W1_1,
                                 const float* __restrict__ W0_2, const float* __restrict__ W1_2,
                                 const float* __restrict__ W0_3, const float* __restrict__ W1_3,
                                 float* __restrict__ Bt) {
    int i = blockIdx.x*blockDim.x + threadIdx.x;   // 6*16384
    int m = i >> 14;
    int r = i & 16383;
    int n = r >> 7, k = r & 127;
    const float* W = (m == 0) ? W0_1 : (m == 1) ? W1_1 : (m == 2) ? W0_2 :
                     (m == 3) ? W1_2 : (m == 4) ? W0_3 : W1_3;
    Bt[i] = rnd_tf32(W[k*128 + n]);
}

// ---------------- image transpose [B,C,H,W] -> [B,H,W,C] ----------------
__global__ void transpose_img(const float* __restrict__ img) {
    __shared__ float tile[32][33];
    int b   = blockIdx.z;
    int hw0 = blockIdx.x * 32;
    int c0  = blockIdx.y * 32;
    int tx = threadIdx.x, ty = threadIdx.y;
    int hw = hw0 + tx, c = c0 + ty;
    if (hw < HWn)
        tile[ty][tx] = img[((size_t)(b*Cn + c))*HWn + hw];
    __syncthreads();
    int hw2 = hw0 + ty, c2 = c0 + tx;
    if (hw2 < HWn)
        g_imgT[((size_t)(b*HWn + hw2))*Cn + c2] = tile[tx][ty];
}

// ---------------- vert_align + add padded -> g_A (tf32-rounded) ----------------
__global__ void vert_align_kernel(const float* __restrict__ vpos,
                                  const float* __restrict__ vpad) {
    int gw   = (blockIdx.x*blockDim.x + threadIdx.x) >> 5;
    int lane = threadIdx.x & 31;
    if (gw >= Mn) return;
    int b = gw / Vn;

    float px = vpos[(size_t)gw*3 + 0];
    float py = vpos[(size_t)gw*3 + 1];
    float x = (px + 1.0f) * 0.5f * (float)(Wn - 1);
    float y = (py + 1.0f) * 0.5f * (float)(Hn - 1);
    float x0f = floorf(x), y0f = floorf(y);
    float wx1 = x - x0f, wx0 = 1.0f - wx1;
    float wy1 = y - y0f, wy0 = 1.0f - wy1;
    int x0 = (int)x0f, y0 = (int)y0f;

    float4 acc = ((const float4*)(vpad + (size_t)gw*Cn))[lane];

    int   xs_[4] = { x0, x0+1, x0,   x0+1 };
    int   ys_[4] = { y0, y0,   y0+1, y0+1 };
    float ws_[4] = { wx0*wy0, wx1*wy0, wx0*wy1, wx1*wy1 };

    #pragma unroll
    for (int t = 0; t < 4; t++) {
        int xi = xs_[t], yi = ys_[t];
        bool inb = (xi >= 0) && (xi < Wn) && (yi >= 0) && (yi < Hn);
        float wgt = inb ? ws_[t] : 0.0f;
        if (wgt != 0.0f) {
            float4 f = ((const float4*)(g_imgT + ((size_t)((b*Hn + yi)*Wn + xi))*Cn))[lane];
            acc.x += wgt*f.x; acc.y += wgt*f.y; acc.z += wgt*f.z; acc.w += wgt*f.w;
        }
    }
    acc.x = rnd_tf32(acc.x); acc.y = rnd_tf32(acc.y);
    acc.z = rnd_tf32(acc.z); acc.w = rnd_tf32(acc.w);
    ((float4*)(g_A + (size_t)gw*Cn))[lane] = acc;
}

// ---------------- tf32 mma.sync dual GEMM: Y0 = X@W0+b0, Y1 = X@W1 ----------------
// 512 threads (16 warps = 4/SMSP), 3-stage sA ring, 1 barrier per tile.
#define TILE_M 64
#define SA_STAGE 8192                       // floats per stage (64x128)
#define SMEM_FLOATS (32768 + 3*SA_STAGE + 128)   // 229,888 B

__device__ __forceinline__ void issue_tile(const float* __restrict__ X, int t, int buf,
                                           int tid, uint32_t sA_u) {
    const float* src0 = X + (size_t)t * (TILE_M * 128);
    uint32_t dbase = sA_u + (uint32_t)buf * (SA_STAGE * 4u);   // bytes
    #pragma unroll
    for (int j = 0; j < 4; j++) {
        int i4 = tid + j*512;            // 0..2047 float4s
        int row = i4 >> 5;
        int kq  = (i4 & 31) << 2;
        uint32_t off = (uint32_t)((row << 7) + (kq ^ ((row & 7) << 2))) * 4u;
        asm volatile("cp.async.cg.shared.global [%0], [%1], 16;"
            :: "r"(dbase + off), "l"(src0 + row*128 + kq));
    }
    asm volatile("cp.async.commit_group;" ::: "memory");
}

__global__ void __launch_bounds__(512, 1)
gemm_dual_mma(const float* __restrict__ X,
              const float* __restrict__ Bt0, const float* __restrict__ Bt1,
              const float* __restrict__ bias,
              float* __restrict__ Y0, float* __restrict__ Y1) {
    extern __shared__ float smf[];
    float* sB    = smf;                    // 32768 floats
    float* sA    = smf + 32768;            // 3 stages x 8192 floats
    float* sbias = smf + 32768 + 3*SA_STAGE;

    int tid = threadIdx.x;

    for (int i4 = tid; i4 < 8192; i4 += 512) {
        int n  = i4 >> 5;
        int kq = (i4 & 31) << 2;
        const float* src = (n < 128) ? (Bt0 + n*128 + kq) : (Bt1 + (n-128)*128 + kq);
        float4 v = *(const float4*)src;
        *(float4*)(sB + n*128 + (kq ^ ((n & 7) << 2))) = v;
    }
    if (tid < 128) sbias[tid] = bias[tid];

    uint32_t sA_u = smem_u32(sA);

    int wid = tid >> 5, lane = tid & 31;
    int gidx = lane >> 2, tig = lane & 3;
    int rowg = wid & 1;                 // 2 row groups x 32 rows
    int colg = wid >> 1;                // 8 col groups x 32 cols
    int m0w = rowg * 32;
    int colbase = colg * 32;            // 0..255 (128..255 -> Y1)
    const uint32_t xsw = (uint32_t)(gidx << 2);

    const int ntot = Mn / TILE_M;               // 10000
    const int grid = gridDim.x;

    // prologue: 2 groups committed (t0 -> buf0, t0+grid -> buf1; empty if OOB)
    int t0 = blockIdx.x;                        // t0 < ntot (grid << ntot)
    issue_tile(X, t0, 0, tid, sA_u);
    if (t0 + grid < ntot) issue_tile(X, t0 + grid, 1, tid, sA_u);
    else asm volatile("cp.async.commit_group;" ::: "memory");

    int it = 0;
    for (int t = t0; t < ntot; t += grid, it++) {
        // wait for buf it%3's group (allow 1 newer pending), then one barrier
        asm volatile("cp.async.wait_group 1;" ::: "memory");
        __syncthreads();

        // prefetch 2 ahead into buf (it+2)%3 — safe: all warps have left iter it-1
        {
            int tn2 = t + 2*grid;
            int b2 = (it + 2) % 3;
            if (tn2 < ntot) issue_tile(X, tn2, b2, tid, sA_u);
            else asm volatile("cp.async.commit_group;" ::: "memory");
        }

        int bcur = it % 3;
        const float* sAb = sA + bcur * SA_STAGE;

        float c[2][4][4];
        #pragma unroll
        for (int mt = 0; mt < 2; mt++)
            #pragma unroll
            for (int nt = 0; nt < 4; nt++)
                #pragma unroll
                for (int q = 0; q < 4; q++) c[mt][nt][q] = 0.0f;

        #pragma unroll
        for (int ks = 0; ks < 16; ks++) {
            int kb = ks * 8;
            uint32_t ka0 = (uint32_t)(kb + tig)     ^ xsw;
            uint32_t ka1 = (uint32_t)(kb + 4 + tig) ^ xsw;

            uint32_t a[2][4];
            #pragma unroll
            for (int mt = 0; mt < 2; mt++) {
                int r0 = m0w + mt*16 + gidx;
                int r1 = r0 + 8;
                a[mt][0] = __float_as_uint(sAb[r0*128 + ka0]);
                a[mt][1] = __float_as_uint(sAb[r1*128 + ka0]);
                a[mt][2] = __float_as_uint(sAb[r0*128 + ka1]);
                a[mt][3] = __float_as_uint(sAb[r1*128 + ka1]);
            }
            uint32_t b[4][2];
            #pragma unroll
            for (int nt = 0; nt < 4; nt++) {
                int n = colbase + nt*8 + gidx;
                b[nt][0] = __float_as_uint(sB[n*128 + ka0]);
                b[nt][1] = __float_as_uint(sB[n*128 + ka1]);
            }
            #pragma unroll
            for (int mt = 0; mt < 2; mt++)
                #pragma unroll
                for (int nt = 0; nt < 4; nt++)
                    mma_tf32(c[mt][nt], a[mt], b[nt]);
        }

        int rowbase = t * TILE_M + m0w + gidx;
        #pragma unroll
        for (int mt = 0; mt < 2; mt++) {
            int row = rowbase + mt*16;
            #pragma unroll
            for (int nt = 0; nt < 4; nt++) {
                int col = colbase + nt*8 + 2*tig;
                float v0 = c[mt][nt][0], v1 = c[mt][nt][1];
                float v2 = c[mt][nt][2], v3 = c[mt][nt][3];
                if (colg < 4) {
                    float bv0 = sbias[col], bv1 = sbias[col + 1];
                    *(float2*)(Y0 + (size_t)row*128 + col)     = make_float2(v0 + bv0, v1 + bv1);
                    *(float2*)(Y0 + (size_t)(row+8)*128 + col) = make_float2(v2 + bv0, v3 + bv1);
                } else {
                    int c1 = col - 128;
                    *(float2*)(Y1 + (size_t)row*128 + c1)      = make_float2(v0, v1);
                    *(float2*)(Y1 + (size_t)(row+8)*128 + c1)  = make_float2(v2, v3);
                }
            }
        }
        // no trailing barrier — next iteration's barrier provides ordering
    }
}

// ---------------- combine (R3 exact): out = T0 (+Dadd) + sum_{j in N(v)} T1[b,j] ----------------
__global__ void combine_kernel(const float* __restrict__ T0,
                               const float* __restrict__ T1,
                               const float* __restrict__ Dadd,
                               float* __restrict__ outp,
                               int do_round) {
    int gw   = (blockIdx.x*blockDim.x + threadIdx.x) >> 5;
    int lane = threadIdx.x & 31;
    if (gw >= Mn) return;
    int b = gw / Vn;
    int v = gw - b*Vn;

    size_t off = (size_t)gw*Cn + lane*4;
    float4 acc = *(const float4*)(T0 + off);
    if (Dadd) {
        float4 d = *(const float4*)(Dadd + off);
        acc.x += d.x; acc.y += d.y; acc.z += d.z; acc.w += d.w;
    }
    int s = g_rowptr[v];
    int e = g_rowptr[v+1];
    const float* baseT1 = T1 + (size_t)b*Vn*Cn + lane*4;
    for (int p = s; p < e; p++) {
        int j = __ldg(&g_col[p]);
        float4 t = *(const float4*)(baseT1 + (size_t)j*Cn);
        acc.x += t.x; acc.y += t.y; acc.z += t.z; acc.w += t.w;
    }
    if (do_round) {
        acc.x = rnd_tf32(acc.x); acc.y = rnd_tf32(acc.y);
        acc.z = rnd_tf32(acc.z); acc.w = rnd_tf32(acc.w);
    }
    *(float4*)(outp + off) = acc;
}

// ---------------- launch ----------------
extern "C" void kernel_launch(void* const* d_in, const int* in_sizes, int n_in,
                              void* d_out, int out_size) {
    const float* img  = (const float*)d_in[0];
    const float* vpos = (const float*)d_in[1];
    const float* vpad = (const float*)d_in[2];
    const int*   edges= (const int*)  d_in[3];
    const float* w0_1 = (const float*)d_in[4];
    const float* b0_1 = (const float*)d_in[5];
    const float* w1_1 = (const float*)d_in[6];
    const float* w0_2 = (const float*)d_in[7];
    const float* b0_2 = (const float*)d_in[8];
    const float* w1_2 = (const float*)d_in[9];
    const float* w0_3 = (const float*)d_in[10];
    const float* b0_3 = (const float*)d_in[11];
    const float* w1_3 = (const float*)d_in[12];
    float* out = (float*)d_out;

    float *pA, *pD, *pT0, *pT1, *pBt;
    cudaGetSymbolAddress((void**)&pA,  g_A);
    cudaGetSymbolAddress((void**)&pD,  g_Dk);
    cudaGetSymbolAddress((void**)&pT0, g_T0);
    cudaGetSymbolAddress((void**)&pT1, g_T1);
    cudaGetSymbolAddress((void**)&pBt, g_Bt);

    const int smem = SMEM_FLOATS * sizeof(float);   // 229,888 B
    cudaFuncSetAttribute(gemm_dual_mma, cudaFuncAttributeMaxDynamicSharedMemorySize, smem);

    int nsm = 148;
    cudaDeviceGetAttribute(&nsm, cudaDevAttrMultiProcessorCount, 0);

    // 1: weights  2: transpose  3: vert_align  4: gemm1  (gemm1 lands in the ncu slot)
    prep_weights_all<<<(6*16384)/256, 256>>>(w0_1, w1_1, w0_2, w1_2, w0_3, w1_3, pBt);
    transpose_img<<<dim3((HWn+31)/32, Cn/32, Bn), dim3(32,32)>>>(img);
    vert_align_kernel<<<Mn/8, 256>>>(vpos, vpad);   // g_A = round(G)
    gemm_dual_mma<<<nsm, 512, smem>>>(pA, pBt + 0*16384, pBt + 1*16384, b0_1, pT0, pT1);

    // CSR build (needed only before combine1)
    zero_csr<<<(Vn+255)/256, 256>>>();
    count_edges<<<(En+255)/256, 256>>>(edges);
    scan_kernel<<<1, 1024>>>();
    fill_edges<<<(En+255)/256, 256>>>(edges);

    // conv1: D = G@W0+b0 + agg(G@W1)
    combine_kernel<<<Mn/8, 256>>>(pT0, pT1, nullptr, pD, 1);

    // conv2: U = D@W0+b0 + agg(D@W1)
    gemm_dual_mma<<<nsm, 512, smem>>>(pD, pBt + 2*16384, pBt + 3*16384, b0_2, pT0, pT1);
    combine_kernel<<<Mn/8, 256>>>(pT0, pT1, nullptr, pA, 1);

    // conv3 + final residual: out = D + (U@W0+b0 + agg(U@W1))
    gemm_dual_mma<<<nsm, 512, smem>>>(pA, pBt + 4*16384, pBt + 5*16384, b0_3, pT0, pT1);
    combine_kernel<<<Mn/8, 256>>>(pT0, pT1, pD, out, 0);
}

// round 12
// speedup vs baseline: 1.0646x; 1.0646x over previous
#include <cuda_runtime.h>
#include <cstdint>

#define Bn 16
#define Vn 40000
#define Cn 128
#define Hn 56
#define Wn 56
#define En 120000
#define Mn (Bn*Vn)          // 640000
#define HWn (Hn*Wn)         // 3136
#define TILE_M 96
#define NTOT ((Mn + TILE_M - 1) / TILE_M)   // 6667 (last tile 32 pad rows)
#define BUF_FLOATS 81928192                  // 640032*128 = 81,924,096 rounded up

// ---------------- device scratch (zero-initialized; pad rows read as 0) ----------------
__device__ float g_imgT[(size_t)Bn*HWn*Cn];     // [B,H,W,C]
__device__ float g_A [BUF_FLOATS];              // G, later U (tf32-rounded)
__device__ float g_Dk[BUF_FLOATS];              // D (tf32-rounded; residual)
__device__ float g_T0[BUF_FLOATS];              // X@W0+b0
__device__ float g_T1[BUF_FLOATS];              // X@W1
__device__ float g_Bt[6*128*128];               // transposed tf32 weights [n][k]

__device__ int g_deg[Vn];
__device__ int g_cursor[Vn];
__device__ int g_rowptr[Vn+1];
__device__ int g_col[2*En];

// ---------------- helpers ----------------
__device__ __forceinline__ float rnd_tf32(float x) {
    float r;
    asm("cvt.rna.tf32.f32 %0, %1;" : "=f"(r) : "f"(x));
    return r;
}

__device__ __forceinline__ uint32_t smem_u32(const void* p) {
    uint32_t a;
    asm("{ .reg .u64 t; cvta.to.shared.u64 t, %1; cvt.u32.u64 %0, t; }" : "=r"(a) : "l"(p));
    return a;
}

__device__ __forceinline__ void mma_tf32(float* c, const uint32_t* a, const uint32_t* b) {
    asm volatile(
        "mma.sync.aligned.m16n8k8.row.col.f32.tf32.tf32.f32 "
        "{%0,%1,%2,%3}, {%4,%5,%6,%7}, {%8,%9}, {%0,%1,%2,%3};"
        : "+f"(c[0]), "+f"(c[1]), "+f"(c[2]), "+f"(c[3])
        : "r"(a[0]), "r"(a[1]), "r"(a[2]), "r"(a[3]), "r"(b[0]), "r"(b[1]));
}

// ---------------- CSR build ----------------
__global__ void zero_csr() {
    int i = blockIdx.x*blockDim.x + threadIdx.x;
    if (i < Vn) { g_deg[i] = 0; g_cursor[i] = 0; }
}

__global__ void count_edges(const int* __restrict__ edges) {
    int e = blockIdx.x*blockDim.x + threadIdx.x;
    if (e < En) {
        atomicAdd(&g_deg[edges[2*e+0]], 1);
        atomicAdd(&g_deg[edges[2*e+1]], 1);
    }
}

__global__ void scan_kernel() {
    __shared__ int partial[1024];
    int t = threadIdx.x;
    const int CH = (Vn + 1023) / 1024;
    int base = t * CH;
    int s = 0;
    for (int i = 0; i < CH; i++) {
        int idx = base + i;
        if (idx < Vn) s += g_deg[idx];
    }
    partial[t] = s;
    __syncthreads();
    for (int off = 1; off < 1024; off <<= 1) {
        int v = 0;
        if (t >= off) v = partial[t - off];
        __syncthreads();
        partial[t] += v;
        __syncthreads();
    }
    int run = (t == 0) ? 0 : partial[t-1];
    for (int i = 0; i < CH; i++) {
        int idx = base + i;
        if (idx < Vn) { g_rowptr[idx] = run; run += g_deg[idx]; }
    }
    if (t == 1023) g_rowptr[Vn] = run;
}

__global__ void fill_edges(const int* __restrict__ edges) {
    int e = blockIdx.x*blockDim.x + threadIdx.x;
    if (e < En) {
        int i = edges[2*e+0], j = edges[2*e+1];
        int p = atomicAdd(&g_cursor[i], 1);
        g_col[g_rowptr[i] + p] = j;
        int q = atomicAdd(&g_cursor[j], 1);
        g_col[g_rowptr[j] + q] = i;
    }
}

// ---------------- weight prep: all 6 matrices in one launch ----------------
__global__ void prep_weights_all(const float* __restrict__ W0_1, const float* __restrict__ W1_1,
                                 const float* __restrict__ W0_2, const float* __restrict__ W1_2,
                                 const float* __restrict__ W0_3, const float* __restrict__ W1_3,
                                 float* __restrict__ Bt) {
    int i = blockIdx.x*blockDim.x + threadIdx.x;   // 6*16384
    int m = i >> 14;
    int r = i & 16383;
    int n = r >> 7, k = r & 127;
    const float* W = (m == 0) ? W0_1 : (m == 1) ? W1_1 : (m == 2) ? W0_2 :
                     (m == 3) ? W1_2 : (m == 4) ? W0_3 : W1_3;
    Bt[i] = rnd_tf32(W[k*128 + n]);
}

// ---------------- image transpose [B,C,H,W] -> [B,H,W,C] ----------------
__global__ void transpose_img(const float* __restrict__ img) {
    __shared__ float tile[32][33];
    int b   = blockIdx.z;
    int hw0 = blockIdx.x * 32;
    int c0  = blockIdx.y * 32;
    int tx = threadIdx.x, ty = threadIdx.y;
    int hw = hw0 + tx, c = c0 + ty;
    if (hw < HWn)
        tile[ty][tx] = img[((size_t)(b*Cn + c))*HWn + hw];
    __syncthreads();
    int hw2 = hw0 + ty, c2 = c0 + tx;
    if (hw2 < HWn)
        g_imgT[((size_t)(b*HWn + hw2))*Cn + c2] = tile[tx][ty];
}

// ---------------- vert_align + add padded -> g_A (tf32-rounded) ----------------
__global__ void vert_align_kernel(const float* __restrict__ vpos,
                                  const float* __restrict__ vpad) {
    int gw   = (blockIdx.x*blockDim.x + threadIdx.x) >> 5;
    int lane = threadIdx.x & 31;
    if (gw >= Mn) return;
    int b = gw / Vn;

    float px = vpos[(size_t)gw*3 + 0];
    float py = vpos[(size_t)gw*3 + 1];
    float x = (px + 1.0f) * 0.5f * (float)(Wn - 1);
    float y = (py + 1.0f) * 0.5f * (float)(Hn - 1);
    float x0f = floorf(x), y0f = floorf(y);
    float wx1 = x - x0f, wx0 = 1.0f - wx1;
    float wy1 = y - y0f, wy0 = 1.0f - wy1;
    int x0 = (int)x0f, y0 = (int)y0f;

    float4 acc = ((const float4*)(vpad + (size_t)gw*Cn))[lane];

    int   xs_[4] = { x0, x0+1, x0,   x0+1 };
    int   ys_[4] = { y0, y0,   y0+1, y0+1 };
    float ws_[4] = { wx0*wy0, wx1*wy0, wx0*wy1, wx1*wy1 };

    #pragma unroll
    for (int t = 0; t < 4; t++) {
        int xi = xs_[t], yi = ys_[t];
        bool inb = (xi >= 0) && (xi < Wn) && (yi >= 0) && (yi < Hn);
        float wgt = inb ? ws_[t] : 0.0f;
        if (wgt != 0.0f) {
            float4 f = ((const float4*)(g_imgT + ((size_t)((b*Hn + yi)*Wn + xi))*Cn))[lane];
            acc.x += wgt*f.x; acc.y += wgt*f.y; acc.z += wgt*f.z; acc.w += wgt*f.w;
        }
    }
    acc.x = rnd_tf32(acc.x); acc.y = rnd_tf32(acc.y);
    acc.z = rnd_tf32(acc.z); acc.w = rnd_tf32(acc.w);
    ((float4*)(g_A + (size_t)gw*Cn))[lane] = acc;
}

// ---------------- tf32 mma.sync dual GEMM: Y0 = X@W0+b0, Y1 = X@W1 ----------------
// 256 threads (8 warps: 2 rowg x 4 colg, mt=3 nt=8), TILE_M=96, 2-stage ring.
#define SA_STAGE (TILE_M*128)                       // 12288 floats per stage
#define SMEM_FLOATS (32768 + 2*SA_STAGE + 128)      // 229,888 B

__device__ __forceinline__ void issue_tile(const float* __restrict__ X, int t, int buf,
                                           int tid, uint32_t sA_u) {
    const float* src0 = X + (size_t)t * (TILE_M * 128);
    uint32_t dbase = sA_u + (uint32_t)buf * (SA_STAGE * 4u);   // bytes
    #pragma unroll
    for (int j = 0; j < 12; j++) {
        int i4 = tid + j*256;            // 0..3071 float4s
        int row = i4 >> 5;               // 0..95
        int kq  = (i4 & 31) << 2;
        uint32_t off = (uint32_t)((row << 7) + (kq ^ ((row & 7) << 2))) * 4u;
        asm volatile("cp.async.cg.shared.global [%0], [%1], 16;"
            :: "r"(dbase + off), "l"(src0 + row*128 + kq));
    }
    asm volatile("cp.async.commit_group;" ::: "memory");
}

__global__ void __launch_bounds__(256, 1)
gemm_dual_mma(const float* __restrict__ X,
              const float* __restrict__ Bt0, const float* __restrict__ Bt1,
              const float* __restrict__ bias,
              float* __restrict__ Y0, float* __restrict__ Y1) {
    extern __shared__ float smf[];
    float* sB    = smf;                    // 32768 floats
    float* sA    = smf + 32768;            // 2 stages x 12288 floats
    float* sbias = smf + 32768 + 2*SA_STAGE;

    int tid = threadIdx.x;

    for (int i4 = tid; i4 < 8192; i4 += 256) {
        int n  = i4 >> 5;
        int kq = (i4 & 31) << 2;
        const float* src = (n < 128) ? (Bt0 + n*128 + kq) : (Bt1 + (n-128)*128 + kq);
        float4 v = *(const float4*)src;
        *(float4*)(sB + n*128 + (kq ^ ((n & 7) << 2))) = v;
    }
    if (tid < 128) sbias[tid] = bias[tid];

    uint32_t sA_u = smem_u32(sA);

    int wid = tid >> 5, lane = tid & 31;
    int gidx = lane >> 2, tig = lane & 3;
    int rowg = wid & 1, colg = wid >> 1;   // 2 row groups x 4 col groups
    int m0w = rowg * 48;                   // 48 rows per row group (mt=3)
    int colbase = colg * 64;               // 0..255 (128..255 -> Y1)
    const uint32_t xsw = (uint32_t)(gidx << 2);

    const int grid = gridDim.x;

    // prologue: stage 0
    int t0 = blockIdx.x;
    issue_tile(X, t0, 0, tid, sA_u);

    int it = 0;
    for (int t = t0; t < NTOT; t += grid, it++) {
        asm volatile("cp.async.wait_group 0;" ::: "memory");
        __syncthreads();   // buf it&1 ready; all warps done with iter it-1

        int tn = t + grid;
        if (tn < NTOT) issue_tile(X, tn, (it + 1) & 1, tid, sA_u);

        const float* sAb = sA + (it & 1) * SA_STAGE;

        float c[3][8][4];
        #pragma unroll
        for (int mt = 0; mt < 3; mt++)
            #pragma unroll
            for (int nt = 0; nt < 8; nt++)
                #pragma unroll
                for (int q = 0; q < 4; q++) c[mt][nt][q] = 0.0f;

        #pragma unroll
        for (int ks = 0; ks < 16; ks++) {
            int kb = ks * 8;
            uint32_t ka0 = (uint32_t)(kb + tig)     ^ xsw;
            uint32_t ka1 = (uint32_t)(kb + 4 + tig) ^ xsw;

            uint32_t a[3][4];
            #pragma unroll
            for (int mt = 0; mt < 3; mt++) {
                int r0 = m0w + mt*16 + gidx;
                int r1 = r0 + 8;
                a[mt][0] = __float_as_uint(sAb[r0*128 + ka0]);
                a[mt][1] = __float_as_uint(sAb[r1*128 + ka0]);
                a[mt][2] = __float_as_uint(sAb[r0*128 + ka1]);
                a[mt][3] = __float_as_uint(sAb[r1*128 + ka1]);
            }
            uint32_t b[8][2];
            #pragma unroll
            for (int nt = 0; nt < 8; nt++) {
                int n = colbase + nt*8 + gidx;
                b[nt][0] = __float_as_uint(sB[n*128 + ka0]);
                b[nt][1] = __float_as_uint(sB[n*128 + ka1]);
            }
            #pragma unroll
            for (int mt = 0; mt < 3; mt++)
                #pragma unroll
                for (int nt = 0; nt < 8; nt++)
                    mma_tf32(c[mt][nt], a[mt], b[nt]);
        }

        int rowbase = t * TILE_M + m0w + gidx;
        #pragma unroll
        for (int mt = 0; mt < 3; mt++) {
            int row = rowbase + mt*16;
            #pragma unroll
            for (int nt = 0; nt < 8; nt++) {
                int col = colbase + nt*8 + 2*tig;
                float v0 = c[mt][nt][0], v1 = c[mt][nt][1];
                float v2 = c[mt][nt][2], v3 = c[mt][nt][3];
                if (colg < 2) {
                    float bv0 = sbias[col], bv1 = sbias[col + 1];
                    *(float2*)(Y0 + (size_t)row*128 + col)     = make_float2(v0 + bv0, v1 + bv1);
                    *(float2*)(Y0 + (size_t)(row+8)*128 + col) = make_float2(v2 + bv0, v3 + bv1);
                } else {
                    int c1 = col - 128;
                    *(float2*)(Y1 + (size_t)row*128 + c1)      = make_float2(v0, v1);
                    *(float2*)(Y1 + (size_t)(row+8)*128 + c1)  = make_float2(v2, v3);
                }
            }
        }
        // next iteration's wait+sync orders buffer reuse vs this epilogue
    }
}

// ---------------- combine (R3 exact): out = T0 (+Dadd) + sum_{j in N(v)} T1[b,j] ----------------
__global__ void combine_kernel(const float* __restrict__ T0,
                               const float* __restrict__ T1,
                               const float* __restrict__ Dadd,
                               float* __restrict__ outp,
                               int do_round) {
    int gw   = (blockIdx.x*blockDim.x + threadIdx.x) >> 5;
    int lane = threadIdx.x & 31;
    if (gw >= Mn) return;
    int b = gw / Vn;
    int v = gw - b*Vn;

    size_t off = (size_t)gw*Cn + lane*4;
    float4 acc = *(const float4*)(T0 + off);
    if (Dadd) {
        float4 d = *(const float4*)(Dadd + off);
        acc.x += d.x; acc.y += d.y; acc.z += d.z; acc.w += d.w;
    }
    int s = g_rowptr[v];
    int e = g_rowptr[v+1];
    const float* baseT1 = T1 + (size_t)b*Vn*Cn + lane*4;
    for (int p = s; p < e; p++) {
        int j = __ldg(&g_col[p]);
        float4 t = *(const float4*)(baseT1 + (size_t)j*Cn);
        acc.x += t.x; acc.y += t.y; acc.z += t.z; acc.w += t.w;
    }
    if (do_round) {
        acc.x = rnd_tf32(acc.x); acc.y = rnd_tf32(acc.y);
        acc.z = rnd_tf32(acc.z); acc.w = rnd_tf32(acc.w);
    }
    *(float4*)(outp + off) = acc;
}

// ---------------- launch ----------------
extern "C" void kernel_launch(void* const* d_in, const int* in_sizes, int n_in,
                              void* d_out, int out_size) {
    const float* img  = (const float*)d_in[0];
    const float* vpos = (const float*)d_in[1];
    const float* vpad = (const float*)d_in[2];
    const int*   edges= (const int*)  d_in[3];
    const float* w0_1 = (const float*)d_in[4];
    const float* b0_1 = (const float*)d_in[5];
    const float* w1_1 = (const float*)d_in[6];
    const float* w0_2 = (const float*)d_in[7];
    const float* b0_2 = (const float*)d_in[8];
    const float* w1_2 = (const float*)d_in[9];
    const float* w0_3 = (const float*)d_in[10];
    const float* b0_3 = (const float*)d_in[11];
    const float* w1_3 = (const float*)d_in[12];
    float* out = (float*)d_out;

    float *pA, *pD, *pT0, *pT1, *pBt;
    cudaGetSymbolAddress((void**)&pA,  g_A);
    cudaGetSymbolAddress((void**)&pD,  g_Dk);
    cudaGetSymbolAddress((void**)&pT0, g_T0);
    cudaGetSymbolAddress((void**)&pT1, g_T1);
    cudaGetSymbolAddress((void**)&pBt, g_Bt);

    const int smem = SMEM_FLOATS * sizeof(float);   // 229,888 B
    cudaFuncSetAttribute(gemm_dual_mma, cudaFuncAttributeMaxDynamicSharedMemorySize, smem);

    int nsm = 148;
    cudaDeviceGetAttribute(&nsm, cudaDevAttrMultiProcessorCount, 0);

    // 1: weights  2: transpose  3: vert_align  4: gemm1  (gemm1 lands in the ncu slot)
    prep_weights_all<<<(6*16384)/256, 256>>>(w0_1, w1_1, w0_2, w1_2, w0_3, w1_3, pBt);
    transpose_img<<<dim3((HWn+31)/32, Cn/32, Bn), dim3(32,32)>>>(img);
    vert_align_kernel<<<Mn/8, 256>>>(vpos, vpad);   // g_A = round(G)
    gemm_dual_mma<<<nsm, 256, smem>>>(pA, pBt + 0*16384, pBt + 1*16384, b0_1, pT0, pT1);

    // CSR build (needed only before combine1)
    zero_csr<<<(Vn+255)/256, 256>>>();
    count_edges<<<(En+255)/256, 256>>>(edges);
    scan_kernel<<<1, 1024>>>();
    fill_edges<<<(En+255)/256, 256>>>(edges);

    // conv1: D = G@W0+b0 + agg(G@W1)
    combine_kernel<<<Mn/8, 256>>>(pT0, pT1, nullptr, pD, 1);

    // conv2: U = D@W0+b0 + agg(D@W1)
    gemm_dual_mma<<<nsm, 256, smem>>>(pD, pBt + 2*16384, pBt + 3*16384, b0_2, pT0, pT1);
    combine_kernel<<<Mn/8, 256>>>(pT0, pT1, nullptr, pA, 1);

    // conv3 + final residual: out = D + (U@W0+b0 + agg(U@W1))
    gemm_dual_mma<<<nsm, 256, smem>>>(pA, pBt + 4*16384, pBt + 5*16384, b0_3, pT0, pT1);
    combine_kernel<<<Mn/8, 256>>>(pT0, pT1, pD, out, 0);
}